// round 13
// baseline (speedup 1.0000x reference)
#include <cuda_runtime.h>

#define BATCH 32
#define LSEQ  2048
#define DDIM  1024
#define NVOC  320
#define NBLK  512
#define NTHR  512

// ---------------------------------------------------------------------------
// R13: globally load-balanced fused kernel. T = sum(len_b) live rows total;
// block k processes live-row interval [k*T/NBLK, (k+1)*T/NBLK), walking the
// per-batch prefix sum. Every block gets equal work (~T/512 ~ 96 rows); ~31
// boundary blocks touch 2 batches (double prologue), the rest 1.
// Per touched batch: redundant histogram + weights (reference is unmasked
// for counts; mask l<len applies to prob), stream live rows, red.global
// into out. vq/lengths are int32 (JAX x64 downcast).
// ---------------------------------------------------------------------------
#define JL       (LSEQ / NTHR)  // 4 positions per thread
#define PF_LINES 3

__global__ void __launch_bounds__(NTHR)
gemv_fused_kernel(const float* __restrict__ feat,
                  const int*   __restrict__ lengths,
                  const int*   __restrict__ vq,
                  float*       __restrict__ out)
{
    __shared__ int   s_cx[NVOC];
    __shared__ int   s_cy[NVOC];
    __shared__ float s_p[LSEQ];     // unnormalized weights of current batch
    __shared__ float s_red[NTHR / 32];
    __shared__ float s_inv;

    const int k   = blockIdx.x;     // 0..NBLK-1
    const int tid = threadIdx.x;    // 0..511

    // ---- Global live-row total and this block's interval -------------------
    int T = 0;
#pragma unroll 4
    for (int b = 0; b < BATCH; b++) T += __ldg(&lengths[b]);

    const int gstart = (int)(((long long)k       * T) / NBLK);
    const int gend   = (int)(((long long)(k + 1) * T) / NBLK);

    const int dlane = tid & 255;    // float4 lane of D
    const int half  = tid >> 8;     // row-parity half

    // ---- Walk batches covered by [gstart, gend) ----------------------------
    int cum = 0;
    for (int b = 0; b < BATCH; b++) {
        const int len  = __ldg(&lengths[b]);
        const int bs   = cum;
        cum += len;
        const int s = max(gstart, bs);
        const int e = min(gend,  cum);
        if (s >= e) continue;                 // block-uniform condition

        const int lstart = s - bs;            // local live-row range in batch b
        const int lend   = e - bs;

        // Batch feature base: input_feature[b, 1, :, :]
        const float* fb = feat + ((size_t)b * 2 + 1) * (size_t)LSEQ * DDIM;

        // -- Prefetch leading rows of our range (fires under the prologue) --
        {
            const char*  base  = reinterpret_cast<const char*>(fb + (size_t)lstart * DDIM);
            const size_t bytes = (size_t)(lend - lstart) * DDIM * 4;
#pragma unroll
            for (int i = 0; i < PF_LINES; i++) {
                const size_t off = ((size_t)tid + (size_t)i * NTHR) * 128;
                if (off < bytes)
                    asm volatile("prefetch.global.L2 [%0];"
                                 :: "l"(base + off) : "memory");
            }
        }

        // -- Phase A: histogram over ALL positions of batch b ---------------
        if (tid < NVOC) { s_cx[tid] = 0; s_cy[tid] = 0; }
        __syncthreads();

        const int4* vq4 = reinterpret_cast<const int4*>(vq) + (size_t)b * (LSEQ / 2);
        int4 vr[JL / 2];
#pragma unroll
        for (int j = 0; j < JL / 2; j++)
            vr[j] = vq4[tid + j * NTHR];
#pragma unroll
        for (int j = 0; j < JL / 2; j++) {
            atomicAdd(&s_cx[vr[j].x], 1);
            atomicAdd(&s_cy[vr[j].y], 1);
            atomicAdd(&s_cx[vr[j].z], 1);
            atomicAdd(&s_cy[vr[j].w], 1);
        }
        __syncthreads();

        // -- Phase B: p = mask/freq, full-batch sum -> 1/sum -----------------
        float lsum = 0.0f;
#pragma unroll
        for (int j = 0; j < JL / 2; j++) {
            const int l0 = 2 * (tid + j * NTHR);
            float p0 = 0.0f, p1 = 0.0f;
            if (l0 < len)
                p0 = __fdividef(1.0f, (float)(s_cx[vr[j].x] + s_cy[vr[j].y]));
            if (l0 + 1 < len)
                p1 = __fdividef(1.0f, (float)(s_cx[vr[j].z] + s_cy[vr[j].w]));
            s_p[l0]     = p0;
            s_p[l0 + 1] = p1;
            lsum += p0 + p1;
        }
#pragma unroll
        for (int o = 16; o > 0; o >>= 1) lsum += __shfl_xor_sync(0xffffffffu, lsum, o);
        if ((tid & 31) == 0) s_red[tid >> 5] = lsum;
        __syncthreads();
        if (tid < NTHR / 32) {
            float ssum = s_red[tid];
#pragma unroll
            for (int o = 8; o > 0; o >>= 1) ssum += __shfl_xor_sync(0xffffu, ssum, o);
            if (tid == 0) s_inv = __fdividef(1.0f, ssum);
        }
        __syncthreads();

        // -- Phase C: stream live rows [lstart, lend), halves by parity ------
        const float4* f4 = reinterpret_cast<const float4*>(fb) + dlane;

        float4 acc = make_float4(0.f, 0.f, 0.f, 0.f);
#pragma unroll 8
        for (int l = lstart + half; l < lend; l += 2) {
            const float  w = s_p[l];
            const float4 v = __ldcs(f4 + (size_t)l * (DDIM / 4));
            acc.x = fmaf(w, v.x, acc.x);
            acc.y = fmaf(w, v.y, acc.y);
            acc.z = fmaf(w, v.z, acc.z);
            acc.w = fmaf(w, v.w, acc.w);
        }

        const float inv = s_inv;
        acc.x *= inv; acc.y *= inv; acc.z *= inv; acc.w *= inv;

        // -- Phase D: vector reduction straight into the output --------------
        float* dst = out + (size_t)b * DDIM + dlane * 4;
        asm volatile("red.global.add.v4.f32 [%0], {%1, %2, %3, %4};"
                     :: "l"(dst), "f"(acc.x), "f"(acc.y), "f"(acc.z), "f"(acc.w)
                     : "memory");
        // Next iteration's first __syncthreads orders s_p reuse after Phase C.
    }
}

// ---------------------------------------------------------------------------
extern "C" void kernel_launch(void* const* d_in, const int* in_sizes, int n_in,
                              void* d_out, int out_size)
{
    const float* feat    = (const float*)d_in[0];
    const int*   lengths = (const int*)d_in[1];
    const int*   vq      = (const int*)d_in[2];
    float*       out     = (float*)d_out;

    (void)in_sizes; (void)n_in;

    // Output is poisoned before timing and accumulated via atomics: zero it.
    cudaMemsetAsync(out, 0, (size_t)out_size * sizeof(float));
    gemv_fused_kernel<<<NBLK, NTHR>>>(feat, lengths, vq, out);
}

// round 14
// speedup vs baseline: 1.2308x; 1.2308x over previous
#include <cuda_runtime.h>

#define BATCH 32
#define LSEQ  2048
#define DDIM  1024
#define NVOC  320
#define LSEG  128
#define NTHR  512
#define NBLK  512   // >= max possible live segments (32*16)

// ---------------------------------------------------------------------------
// R14: R12 streaming body + compact live-segment mapping.
// Live segments (those overlapping [0, len_b)) are flattened into a
// contiguous list; block k handles the k-th live segment, blocks past the
// end exit. Dead blocks are the contiguous grid tail -> live blocks land
// 2-or-3 per SM deterministically (contiguous-modular CTA placement),
// eliminating R12's binomial per-SM imbalance.
// vq_indices / input_lengths are int32 (JAX x64 downcast).
// ---------------------------------------------------------------------------
#define JL       (LSEQ / NTHR)  // 4 positions per thread
#define PF_LINES 3

__global__ void __launch_bounds__(NTHR)
gemv_fused_kernel(const float* __restrict__ feat,
                  const int*   __restrict__ lengths,
                  const int*   __restrict__ vq,
                  float*       __restrict__ out)
{
    __shared__ int   s_cx[NVOC];
    __shared__ int   s_cy[NVOC];
    __shared__ float s_p[LSEQ];     // unnormalized per-position weights
    __shared__ float s_red[NTHR / 32];
    __shared__ float s_inv;

    const int k   = blockIdx.x;
    const int tid = threadIdx.x;

    // ---- Map block k -> k-th live segment (b, split) ----------------------
    int b = -1, split = 0, len = 0;
    {
        int cum = 0;
#pragma unroll
        for (int bb = 0; bb < BATCH; bb++) {
            const int lb = __ldg(&lengths[bb]);
            const int ns = (lb + LSEG - 1) / LSEG;   // live segments in batch bb
            if (b < 0 && k < cum + ns) { b = bb; split = k - cum; len = lb; }
            cum += ns;
        }
        if (b < 0) return;   // k >= total live segments (block-uniform)
    }
    const int seg_start = split * LSEG;
    const int rows_eff  = min(LSEG, len - seg_start);

    // Segment base: input_feature[b, 1, seg_start, :]  (N=2, take last)
    const float* seg = feat + ((size_t)b * 2 + 1) * (size_t)LSEQ * DDIM
                            + (size_t)seg_start * DDIM;

    // ---- Phase 0: L2 prefetch of leading LIVE rows -------------------------
    {
        const size_t live_bytes = (size_t)rows_eff * DDIM * 4;
        const char*  base = reinterpret_cast<const char*>(seg);
#pragma unroll
        for (int i = 0; i < PF_LINES; i++) {
            const size_t off = ((size_t)tid + (size_t)i * NTHR) * 128;
            if (off < live_bytes)
                asm volatile("prefetch.global.L2 [%0];"
                             :: "l"(base + off) : "memory");
        }
    }

    // ---- Hoisted vq loads (int4: two (x,y) pairs per 16B) ------------------
    const int4* vq4 = reinterpret_cast<const int4*>(vq) + (size_t)b * (LSEQ / 2);
    int4 vr[JL / 2];
#pragma unroll
    for (int j = 0; j < JL / 2; j++)
        vr[j] = vq4[tid + j * NTHR];

    // ---- Phase A: histogram over ALL positions (reference is unmasked) ----
    if (tid < NVOC) { s_cx[tid] = 0; s_cy[tid] = 0; }
    __syncthreads();

#pragma unroll
    for (int j = 0; j < JL / 2; j++) {
        atomicAdd(&s_cx[vr[j].x], 1);
        atomicAdd(&s_cy[vr[j].y], 1);
        atomicAdd(&s_cx[vr[j].z], 1);
        atomicAdd(&s_cy[vr[j].w], 1);
    }
    __syncthreads();

    // ---- Phase B: per-position p = mask / freq, block sum -> 1/sum --------
    float lsum = 0.0f;
#pragma unroll
    for (int j = 0; j < JL / 2; j++) {
        const int l0 = 2 * (tid + j * NTHR);
        float p0 = 0.0f, p1 = 0.0f;
        if (l0 < len)
            p0 = __fdividef(1.0f, (float)(s_cx[vr[j].x] + s_cy[vr[j].y]));
        if (l0 + 1 < len)
            p1 = __fdividef(1.0f, (float)(s_cx[vr[j].z] + s_cy[vr[j].w]));
        s_p[l0]     = p0;
        s_p[l0 + 1] = p1;
        lsum += p0 + p1;
    }
#pragma unroll
    for (int o = 16; o > 0; o >>= 1) lsum += __shfl_xor_sync(0xffffffffu, lsum, o);
    if ((tid & 31) == 0) s_red[tid >> 5] = lsum;
    __syncthreads();
    if (tid < NTHR / 32) {   // 16 partials
        float s = s_red[tid];
#pragma unroll
        for (int o = 8; o > 0; o >>= 1) s += __shfl_xor_sync(0xffffu, s, o);
        if (tid == 0) s_inv = __fdividef(1.0f, s);
    }
    __syncthreads();

    // ---- Phase C: stream LIVE rows, two thread-halves interleaved by parity
    const int dlane = tid & 255;
    const int half  = tid >> 8;

    const float4* f4 = reinterpret_cast<const float4*>(seg)
                       + (size_t)half * (DDIM / 4) + dlane;
    const float*  pw = &s_p[seg_start + half];

    float4 acc = make_float4(0.f, 0.f, 0.f, 0.f);
#pragma unroll 8
    for (int l = half; l < rows_eff; l += 2) {
        const float  w = pw[l - half];
        const float4 v = __ldcs(f4 + (size_t)(l - half) * (DDIM / 4));
        acc.x = fmaf(w, v.x, acc.x);
        acc.y = fmaf(w, v.y, acc.y);
        acc.z = fmaf(w, v.z, acc.z);
        acc.w = fmaf(w, v.w, acc.w);
    }

    const float inv = s_inv;
    acc.x *= inv; acc.y *= inv; acc.z *= inv; acc.w *= inv;

    // ---- Phase D: vector reduction straight into the output ----------------
    float* dst = out + (size_t)b * DDIM + dlane * 4;
    asm volatile("red.global.add.v4.f32 [%0], {%1, %2, %3, %4};"
                 :: "l"(dst), "f"(acc.x), "f"(acc.y), "f"(acc.z), "f"(acc.w)
                 : "memory");
}

// ---------------------------------------------------------------------------
extern "C" void kernel_launch(void* const* d_in, const int* in_sizes, int n_in,
                              void* d_out, int out_size)
{
    const float* feat    = (const float*)d_in[0];
    const int*   lengths = (const int*)d_in[1];
    const int*   vq      = (const int*)d_in[2];
    float*       out     = (float*)d_out;

    (void)in_sizes; (void)n_in;

    // Output is poisoned before timing and accumulated via atomics: zero it.
    cudaMemsetAsync(out, 0, (size_t)out_size * sizeof(float));
    gemv_fused_kernel<<<NBLK, NTHR>>>(feat, lengths, vq, out);
}

// round 15
// speedup vs baseline: 1.2910x; 1.0490x over previous
#include <cuda_runtime.h>

#define BATCH 32
#define LSEQ  2048
#define DDIM  1024
#define NVOC  320
#define SPLIT 16
#define LSEG  (LSEQ / SPLIT)   // 128
#define NTHR  512

// ---------------------------------------------------------------------------
// R15: exact R12 body, grid transposed to (BATCH, SPLIT).
// bid = b + 32*split puts each SM's 4 resident blocks in 4 different split
// tiers -> ~3 live + 1 dead per SM uniformly, removing R12's binomial
// live-blocks-per-SM tail (dead = segment beyond len_b, exits at t=0).
// vq_indices / input_lengths are int32 (JAX x64 downcast).
// ---------------------------------------------------------------------------
#define JL       (LSEQ / NTHR)  // 4 positions per thread
#define PF_LINES 3

__global__ void __launch_bounds__(NTHR)
gemv_fused_kernel(const float* __restrict__ feat,
                  const int*   __restrict__ lengths,
                  const int*   __restrict__ vq,
                  float*       __restrict__ out)
{
    __shared__ int   s_cx[NVOC];
    __shared__ int   s_cy[NVOC];
    __shared__ float s_p[LSEQ];     // unnormalized per-position weights
    __shared__ float s_red[NTHR / 32];
    __shared__ float s_inv;

    const int b     = blockIdx.x;   // 0..BATCH-1  (fastest -> split tiers spread per SM)
    const int split = blockIdx.y;   // 0..SPLIT-1
    const int tid   = threadIdx.x;  // 0..511

    // Mask-aware early exit: this block's segment contributes nothing.
    const int len       = lengths[b];
    const int seg_start = split * LSEG;
    if (seg_start >= len) return;
    const int rows_eff  = min(LSEG, len - seg_start);

    // Segment base: input_feature[b, 1, seg_start, :]  (N=2, take last)
    const float* seg = feat + ((size_t)b * 2 + 1) * (size_t)LSEQ * DDIM
                            + (size_t)seg_start * DDIM;

    // ---- Phase 0: L2 prefetch of leading LIVE rows --------------------------
    {
        const size_t live_bytes = (size_t)rows_eff * DDIM * 4;
        const char*  base = reinterpret_cast<const char*>(seg);
#pragma unroll
        for (int i = 0; i < PF_LINES; i++) {
            const size_t off = ((size_t)tid + (size_t)i * NTHR) * 128;
            if (off < live_bytes)
                asm volatile("prefetch.global.L2 [%0];"
                             :: "l"(base + off) : "memory");
        }
    }

    // ---- Hoisted vq loads (int4: two (x,y) pairs per 16B) -------------------
    const int4* vq4 = reinterpret_cast<const int4*>(vq) + (size_t)b * (LSEQ / 2);
    int4 vr[JL / 2];
#pragma unroll
    for (int j = 0; j < JL / 2; j++)
        vr[j] = vq4[tid + j * NTHR];

    // ---- Phase A: histogram over ALL positions (reference is unmasked) ----
    if (tid < NVOC) { s_cx[tid] = 0; s_cy[tid] = 0; }   // NTHR=512 > NVOC=320
    __syncthreads();

#pragma unroll
    for (int j = 0; j < JL / 2; j++) {
        atomicAdd(&s_cx[vr[j].x], 1);
        atomicAdd(&s_cy[vr[j].y], 1);
        atomicAdd(&s_cx[vr[j].z], 1);
        atomicAdd(&s_cy[vr[j].w], 1);
    }
    __syncthreads();

    // ---- Phase B: per-position p = mask / freq, block sum -> 1/sum ----
    float lsum = 0.0f;
#pragma unroll
    for (int j = 0; j < JL / 2; j++) {
        const int l0 = 2 * (tid + j * NTHR);
        float p0 = 0.0f, p1 = 0.0f;
        if (l0 < len)
            p0 = __fdividef(1.0f, (float)(s_cx[vr[j].x] + s_cy[vr[j].y]));
        if (l0 + 1 < len)
            p1 = __fdividef(1.0f, (float)(s_cx[vr[j].z] + s_cy[vr[j].w]));
        s_p[l0]     = p0;
        s_p[l0 + 1] = p1;
        lsum += p0 + p1;
    }
#pragma unroll
    for (int o = 16; o > 0; o >>= 1) lsum += __shfl_xor_sync(0xffffffffu, lsum, o);
    if ((tid & 31) == 0) s_red[tid >> 5] = lsum;
    __syncthreads();
    if (tid < NTHR / 32) {   // 16 partials
        float s = s_red[tid];
#pragma unroll
        for (int o = 8; o > 0; o >>= 1) s += __shfl_xor_sync(0xffffu, s, o);
        if (tid == 0) s_inv = __fdividef(1.0f, s);
    }
    __syncthreads();

    // ---- Phase C: stream LIVE rows, two thread-halves interleaved by parity
    const int dlane = tid & 255;
    const int half  = tid >> 8;

    const float4* f4 = reinterpret_cast<const float4*>(seg)
                       + (size_t)half * (DDIM / 4) + dlane;
    const float*  pw = &s_p[seg_start + half];

    float4 acc = make_float4(0.f, 0.f, 0.f, 0.f);
#pragma unroll 8
    for (int l = half; l < rows_eff; l += 2) {
        const float  w = pw[l - half];
        const float4 v = __ldcs(f4 + (size_t)(l - half) * (DDIM / 4));
        acc.x = fmaf(w, v.x, acc.x);
        acc.y = fmaf(w, v.y, acc.y);
        acc.z = fmaf(w, v.z, acc.z);
        acc.w = fmaf(w, v.w, acc.w);
    }

    const float inv = s_inv;
    acc.x *= inv; acc.y *= inv; acc.z *= inv; acc.w *= inv;

    // ---- Phase D: vector reduction straight into the output ----------------
    float* dst = out + (size_t)b * DDIM + dlane * 4;
    asm volatile("red.global.add.v4.f32 [%0], {%1, %2, %3, %4};"
                 :: "l"(dst), "f"(acc.x), "f"(acc.y), "f"(acc.z), "f"(acc.w)
                 : "memory");
}

// ---------------------------------------------------------------------------
extern "C" void kernel_launch(void* const* d_in, const int* in_sizes, int n_in,
                              void* d_out, int out_size)
{
    const float* feat    = (const float*)d_in[0];
    const int*   lengths = (const int*)d_in[1];
    const int*   vq      = (const int*)d_in[2];
    float*       out     = (float*)d_out;

    (void)in_sizes; (void)n_in;

    // Output is poisoned before timing and accumulated via atomics: zero it.
    cudaMemsetAsync(out, 0, (size_t)out_size * sizeof(float));
    gemv_fused_kernel<<<dim3(BATCH, SPLIT), NTHR>>>(feat, lengths, vq, out);
}